// round 11
// baseline (speedup 1.0000x reference)
#include <cuda_runtime.h>
#include <cuda_bf16.h>
#include <math.h>
#include <stdint.h>

#define BB 2
#define NN 2048
#define DD 512
#define HH 8
#define DH 64
#define INNER 512
#define ROWS (BB*NN)            // 4096
#define BHN ((size_t)BB*HH*NN*DH)
#define WSZ (INNER*DD)          // 262144 = 2^18

// -------- scratch (device globals; no allocation allowed) --------
__device__ float g_lin[3*ROWS*INNER];          // pointwise-conv outputs (fp32)
__device__ __nv_bfloat16 g_xnb[ROWS*DD];       // LN out, big
__device__ __nv_bfloat16 g_xns[ROWS*DD];       // LN out, small
__device__ __nv_bfloat16 g_wb[4*WSZ];          // wq1,wk1,wv1,wout big
__device__ __nv_bfloat16 g_ws[4*WSZ];          // small
__device__ __nv_bfloat16 g_qb[BHN], g_qs[BHN]; // q split, [b][h][n][d]
__device__ __nv_bfloat16 g_kb[BHN], g_ks[BHN]; // k split, [b][h][n][d]
__device__ __nv_bfloat16 g_vbT[BHN], g_vsT[BHN]; // v split, TRANSPOSED [b][h][d][n]
__device__ __nv_bfloat16 g_ob[ROWS*INNER], g_os[ROWS*INNER]; // attn out split

// ---------------- helpers ----------------
__device__ __forceinline__ uint32_t smem_u32(const void* p) {
    uint32_t a;
    asm("{ .reg .u64 t; cvta.to.shared.u64 t, %1; cvt.u32.u64 %0, t; }" : "=r"(a) : "l"(p));
    return a;
}
__device__ __forceinline__ void mma_bf16(float* c, const uint32_t* a, const uint32_t* b) {
    asm volatile(
        "mma.sync.aligned.m16n8k16.row.col.f32.bf16.bf16.f32 "
        "{%0,%1,%2,%3}, {%4,%5,%6,%7}, {%8,%9}, {%0,%1,%2,%3};"
        : "+f"(c[0]), "+f"(c[1]), "+f"(c[2]), "+f"(c[3])
        : "r"(a[0]), "r"(a[1]), "r"(a[2]), "r"(a[3]), "r"(b[0]), "r"(b[1]));
}
#define LDSM_X4(r0, r1, r2, r3, addr) \
    asm volatile("ldmatrix.sync.aligned.m8n8.x4.shared.b16 {%0,%1,%2,%3}, [%4];" \
                 : "=r"(r0), "=r"(r1), "=r"(r2), "=r"(r3) : "r"(addr))
__device__ __forceinline__ void split1(float x, __nv_bfloat16& b, __nv_bfloat16& s) {
    b = __float2bfloat16(x);
    s = __float2bfloat16(x - __bfloat162float(b));
}
__device__ __forceinline__ void split2(float x0, float x1, uint32_t& b, uint32_t& s) {
    __nv_bfloat162 tb = __float22bfloat162_rn(make_float2(x0, x1));
    float2 tf = __bfloat1622float2(tb);
    __nv_bfloat162 ts = __float22bfloat162_rn(make_float2(x0 - tf.x, x1 - tf.y));
    b = *reinterpret_cast<uint32_t*>(&tb);
    s = *reinterpret_cast<uint32_t*>(&ts);
}
#define CP_ASYNC16(dst, src) \
    asm volatile("cp.async.cg.shared.global [%0], [%1], 16;" :: "r"(dst), "l"(src) : "memory")
#define CP_COMMIT() asm volatile("cp.async.commit_group;" ::: "memory")
#define CP_WAIT(n)  asm volatile("cp.async.wait_group %0;" :: "n"(n) : "memory")

// ---------------- LayerNorm -> split bf16 ----------------
__global__ void ln_kernel(const float* __restrict__ x,
                          const float* __restrict__ gamma,
                          const float* __restrict__ beta,
                          __nv_bfloat16* __restrict__ xnb,
                          __nv_bfloat16* __restrict__ xns) {
    int row = blockIdx.x;
    const float* xr = x + (size_t)row * DD;
    int t = threadIdx.x;
    float v0 = xr[t], v1 = xr[t + 256];
    float s = v0 + v1;
    float sq = v0 * v0 + v1 * v1;
    #pragma unroll
    for (int o = 16; o > 0; o >>= 1) {
        s  += __shfl_xor_sync(0xffffffffu, s, o);
        sq += __shfl_xor_sync(0xffffffffu, sq, o);
    }
    __shared__ float ss[8], ssq[8];
    if ((t & 31) == 0) { ss[t >> 5] = s; ssq[t >> 5] = sq; }
    __syncthreads();
    s = 0.f; sq = 0.f;
    #pragma unroll
    for (int i = 0; i < 8; ++i) { s += ss[i]; sq += ssq[i]; }
    float mean = s * (1.f / DD);
    float var  = sq * (1.f / DD) - mean * mean;
    float rstd = rsqrtf(var + 1e-5f);
    float y0 = (v0 - mean) * rstd * gamma[t]       + beta[t];
    float y1 = (v1 - mean) * rstd * gamma[t + 256] + beta[t + 256];
    __nv_bfloat16 b, sm;
    split1(y0, b, sm); xnb[(size_t)row * DD + t] = b;       xns[(size_t)row * DD + t] = sm;
    split1(y1, b, sm); xnb[(size_t)row * DD + t + 256] = b; xns[(size_t)row * DD + t + 256] = sm;
}

// ---------------- weight split (vectorized) ----------------
__global__ void wsplit_kernel(const float* __restrict__ wq1, const float* __restrict__ wk1,
                              const float* __restrict__ wv1, const float* __restrict__ wout,
                              __nv_bfloat16* __restrict__ wb, __nv_bfloat16* __restrict__ ws) {
    int idx = blockIdx.x * 256 + threadIdx.x;       // over 4*WSZ/4
    int sel = idx >> 16;
    int off = idx & 65535;
    const float* src = (sel == 0) ? wq1 : (sel == 1) ? wk1 : (sel == 2) ? wv1 : wout;
    float4 v = ((const float4*)src)[off];
    uint32_t b01, s01, b23, s23;
    split2(v.x, v.y, b01, s01);
    split2(v.z, v.w, b23, s23);
    ((uint2*)wb)[idx] = make_uint2(b01, b23);
    ((uint2*)ws)[idx] = make_uint2(s01, s23);
}

// ---------------- bf16x3 mma.sync GEMM (ldmatrix fragments) ----------------
#define GW 20
#define GTB (128 * GW * 4)
#define SM_GEMM (2 * 4 * GTB)

__global__ void __launch_bounds__(256)
gemm_bf16(const __nv_bfloat16* __restrict__ Abig, const __nv_bfloat16* __restrict__ Asml,
          const __nv_bfloat16* __restrict__ wb,   const __nv_bfloat16* __restrict__ ws,
          size_t w_stride, float* __restrict__ Cbase, size_t c_stride) {
    const __nv_bfloat16* Wb = wb + blockIdx.z * w_stride;
    const __nv_bfloat16* Ws = ws + blockIdx.z * w_stride;
    float* C = Cbase + blockIdx.z * c_stride;

    extern __shared__ char smc[];
    uint32_t smb = smem_u32(smc);
    int tid = threadIdx.x;
    int wid = tid >> 5, lane = tid & 31;
    int wm = wid >> 2, wn = wid & 3;
    int lq = lane >> 2, lm = lane & 3;
    int m0 = blockIdx.y * 128, e0 = blockIdx.x * 128;

    int lrow = tid >> 1;
    int lc2  = (tid & 1) * 2;

    // ldmatrix per-lane row/byte offsets (within a tile array)
    int arow = wm * 64 + (lane & 7) + ((lane >> 3) & 1) * 8;   // + mt*16
    uint32_t aoff = (uint32_t)(arow * GW) * 4 + (uint32_t)(lane >> 4) * 16;   // + kb*4
    int brow = wn * 32 + (lane & 7) + (lane >> 4) * 8;          // + ntp*16
    uint32_t boff = (uint32_t)(brow * GW) * 4 + (uint32_t)((lane >> 3) & 1) * 16;

    float acc[4][4][4];
    #pragma unroll
    for (int i = 0; i < 4; ++i)
        #pragma unroll
        for (int j = 0; j < 4; ++j)
            #pragma unroll
            for (int q = 0; q < 4; ++q) acc[i][j][q] = 0.f;

    auto load_chunk = [&](int c, int buf) {
        int k0 = c << 5;
        uint32_t base = smb + buf * 4 * GTB;
        const __nv_bfloat16* a0 = Abig + (size_t)(m0 + lrow) * 512 + k0;
        const __nv_bfloat16* a1 = Asml + (size_t)(m0 + lrow) * 512 + k0;
        const __nv_bfloat16* w0 = Wb + (size_t)(e0 + lrow) * 512 + k0;
        const __nv_bfloat16* w1 = Ws + (size_t)(e0 + lrow) * 512 + k0;
        #pragma unroll
        for (int j = 0; j < 2; ++j) {
            int c4 = lc2 + j;
            uint32_t doff = (uint32_t)(lrow * GW + c4 * 4) * 4;
            CP_ASYNC16(base + doff,             a0 + c4 * 8);
            CP_ASYNC16(base + GTB + doff,       a1 + c4 * 8);
            CP_ASYNC16(base + 2 * GTB + doff,   w0 + c4 * 8);
            CP_ASYNC16(base + 3 * GTB + doff,   w1 + c4 * 8);
        }
    };

    load_chunk(0, 0);
    CP_COMMIT();

    for (int c = 0; c < 16; ++c) {
        if (c + 1 < 16) {
            load_chunk(c + 1, (c + 1) & 1);
            CP_COMMIT();
            CP_WAIT(1);
        } else {
            CP_WAIT(0);
        }
        __syncthreads();
        uint32_t baseAb = smb + (c & 1) * 4 * GTB;
        uint32_t baseAs = baseAb + GTB;
        uint32_t baseWb = baseAb + 2 * GTB;
        uint32_t baseWs = baseAb + 3 * GTB;
        #pragma unroll
        for (int ks = 0; ks < 2; ++ks) {
            uint32_t kb4 = (uint32_t)(ks * 8) * 4;
            uint32_t ab[4][4], as_[4][4], bb[4][2], bs[4][2];
            #pragma unroll
            for (int mt = 0; mt < 4; ++mt) {
                uint32_t ao = aoff + (uint32_t)(mt * 16 * GW) * 4 + kb4;
                LDSM_X4(ab[mt][0], ab[mt][1], ab[mt][2], ab[mt][3], baseAb + ao);
                LDSM_X4(as_[mt][0], as_[mt][1], as_[mt][2], as_[mt][3], baseAs + ao);
            }
            #pragma unroll
            for (int ntp = 0; ntp < 2; ++ntp) {
                uint32_t bo = boff + (uint32_t)(ntp * 16 * GW) * 4 + kb4;
                LDSM_X4(bb[2*ntp][0], bb[2*ntp][1], bb[2*ntp+1][0], bb[2*ntp+1][1], baseWb + bo);
                LDSM_X4(bs[2*ntp][0], bs[2*ntp][1], bs[2*ntp+1][0], bs[2*ntp+1][1], baseWs + bo);
            }
            #pragma unroll
            for (int mt = 0; mt < 4; ++mt)
                #pragma unroll
                for (int nt = 0; nt < 4; ++nt) {
                    mma_bf16(acc[mt][nt], ab[mt],  bb[nt]);
                    mma_bf16(acc[mt][nt], as_[mt], bb[nt]);
                    mma_bf16(acc[mt][nt], ab[mt],  bs[nt]);
                }
        }
        __syncthreads();
    }

    #pragma unroll
    for (int mt = 0; mt < 4; ++mt) {
        int r0 = m0 + wm * 64 + mt * 16 + lq;
        #pragma unroll
        for (int nt = 0; nt < 4; ++nt) {
            int c0 = e0 + wn * 32 + nt * 8 + lm * 2;
            *(float2*)(C + (size_t)r0 * 512 + c0)       = make_float2(acc[mt][nt][0], acc[mt][nt][1]);
            *(float2*)(C + (size_t)(r0 + 8) * 512 + c0) = make_float2(acc[mt][nt][2], acc[mt][nt][3]);
        }
    }
}

// ------- depthwise conv q,k (vectorized float4) + split -------
__global__ void conv_qk(const float* __restrict__ lin,
                        const float* __restrict__ wqd, const float* __restrict__ wkd,
                        __nv_bfloat16* __restrict__ qb, __nv_bfloat16* __restrict__ qs,
                        __nv_bfloat16* __restrict__ kb, __nv_bfloat16* __restrict__ ks) {
    int idx = blockIdx.x * 256 + threadIdx.x;      // over ROWS*INNER/4
    int e4 = idx & 127;
    int n  = (idx >> 7) & (NN - 1);
    int b  = idx >> 18;
    int e  = e4 << 2;
    int h = e >> 6, d = e & 63;
    size_t dstu2 = ((((size_t)(b * HH + h) * NN + n) * DH + d)) >> 2;
    const float4* L4 = (const float4*)lin;
    const float4 z4 = make_float4(0.f, 0.f, 0.f, 0.f);
    #pragma unroll
    for (int t = 0; t < 2; ++t) {
        const float4* L = L4 + (size_t)t * (ROWS * INNER / 4);
        const float* wd = t ? wkd : wqd;
        float4 y2 = L[idx];
        float4 y1 = (n >= 1) ? L[idx - 128] : z4;
        float4 y0 = (n >= 2) ? L[idx - 256] : z4;
        float v[4];
        v[0] = wd[e*3+0]*y0.x + wd[e*3+1]*y1.x + wd[e*3+2]*y2.x;
        v[1] = wd[e*3+3]*y0.y + wd[e*3+4]*y1.y + wd[e*3+5]*y2.y;
        v[2] = wd[e*3+6]*y0.z + wd[e*3+7]*y1.z + wd[e*3+8]*y2.z;
        v[3] = wd[e*3+9]*y0.w + wd[e*3+10]*y1.w + wd[e*3+11]*y2.w;
        if (t == 0) { v[0] *= 0.125f; v[1] *= 0.125f; v[2] *= 0.125f; v[3] *= 0.125f; }
        uint32_t b01, s01, b23, s23;
        split2(v[0], v[1], b01, s01);
        split2(v[2], v[3], b23, s23);
        if (t == 0) {
            ((uint2*)qb)[dstu2] = make_uint2(b01, b23);
            ((uint2*)qs)[dstu2] = make_uint2(s01, s23);
        } else {
            ((uint2*)kb)[dstu2] = make_uint2(b01, b23);
            ((uint2*)ks)[dstu2] = make_uint2(s01, s23);
        }
    }
}

// ------- depthwise conv for v + TRANSPOSED split output -------
__global__ void conv_v(const float* __restrict__ lin2, const float* __restrict__ wvd,
                       __nv_bfloat16* __restrict__ vbT, __nv_bfloat16* __restrict__ vsT) {
    __shared__ float tile[34 * 33];
    int b = blockIdx.z, e0 = blockIdx.y * 32, n0 = blockIdx.x * 32;
    int tid = threadIdx.x;
    for (int i = tid; i < 34 * 32; i += 256) {
        int r = i >> 5, c = i & 31;
        int n = n0 - 2 + r;
        tile[r * 33 + c] = (n >= 0) ? lin2[((size_t)b * NN + n) * INNER + e0 + c] : 0.f;
    }
    __syncthreads();
    int nl = tid & 31;
    #pragma unroll
    for (int p = 0; p < 4; ++p) {
        int el = (tid >> 5) + p * 8;
        int eg = e0 + el;
        int h = eg >> 6, d = eg & 63;
        float y0 = tile[nl * 33 + el];
        float y1 = tile[(nl + 1) * 33 + el];
        float y2 = tile[(nl + 2) * 33 + el];
        float v = wvd[eg * 3 + 0] * y0 + wvd[eg * 3 + 1] * y1 + wvd[eg * 3 + 2] * y2;
        __nv_bfloat16 big, sml;
        split1(v, big, sml);
        size_t dst = ((size_t)(b * HH + h) * DH + d) * NN + n0 + nl;
        vbT[dst] = big; vsT[dst] = sml;
    }
}

// ---------------- Flash attention: bf16x3, ldmatrix, prefetch ----------------
// Br=Bc=64, 128 threads (4 warps x 16 rows). Double-buffered K/V tiles.
#define AW 36
#define SETU (4 * 64 * AW)              // u32 per buffer set (Kb,Ks,Vb,Vs)
#define SMEM_ATTN (2 * SETU * 4)        // 73728 B -> 3 blocks/SM

__global__ void __launch_bounds__(128, 3)
attn_kernel(const __nv_bfloat16* __restrict__ qb_g, const __nv_bfloat16* __restrict__ qs_g,
            const __nv_bfloat16* __restrict__ kb_g, const __nv_bfloat16* __restrict__ ks_g,
            const __nv_bfloat16* __restrict__ vbT_g, const __nv_bfloat16* __restrict__ vsT_g,
            __nv_bfloat16* __restrict__ ob_g, __nv_bfloat16* __restrict__ os_g) {
    extern __shared__ uint32_t smu[];
    uint32_t smb = smem_u32(smu);

    int qt = gridDim.x - 1 - blockIdx.x;   // big tiles first
    int bh = blockIdx.y;
    int b = bh >> 3, h = bh & 7;
    int qs0 = qt * 64;

    int tid = threadIdx.x;
    int wid = tid >> 5, lane = tid & 31;
    int lq = lane >> 2, lm = lane & 3;
    int wr = wid * 16;

    // ldmatrix per-lane offset within a K/V tile (row = nt*8 + (lane&7))
    uint32_t lmo = (uint32_t)((lane & 7) * AW) * 4 + (uint32_t)(lane >> 3) * 16;

    // Q fragments direct from global (packed u32 = 2 bf16 over d)
    const uint32_t* qbu = (const uint32_t*)qb_g + (size_t)bh * NN * 32;
    const uint32_t* qsu = (const uint32_t*)qs_g + (size_t)bh * NN * 32;
    int r0 = qs0 + wr + lq;
    uint32_t qbf[4][4], qsf[4][4];
    #pragma unroll
    for (int ks = 0; ks < 4; ++ks) {
        qbf[ks][0] = qbu[(size_t)r0 * 32 + ks * 8 + lm];
        qbf[ks][1] = qbu[(size_t)(r0 + 8) * 32 + ks * 8 + lm];
        qbf[ks][2] = qbu[(size_t)r0 * 32 + ks * 8 + lm + 4];
        qbf[ks][3] = qbu[(size_t)(r0 + 8) * 32 + ks * 8 + lm + 4];
        qsf[ks][0] = qsu[(size_t)r0 * 32 + ks * 8 + lm];
        qsf[ks][1] = qsu[(size_t)(r0 + 8) * 32 + ks * 8 + lm];
        qsf[ks][2] = qsu[(size_t)r0 * 32 + ks * 8 + lm + 4];
        qsf[ks][3] = qsu[(size_t)(r0 + 8) * 32 + ks * 8 + lm + 4];
    }

    float acc_o[8][4];
    #pragma unroll
    for (int nt = 0; nt < 8; ++nt)
        #pragma unroll
        for (int q = 0; q < 4; ++q) acc_o[nt][q] = 0.f;
    float m0r = -1e30f, m1r = -1e30f, l0r = 0.f, l1r = 0.f;
    float slope = exp2f(-(float)(h + 1));
    int ig0 = r0, ig1 = r0 + 8;

    const char* kbp = (const char*)(kb_g + (size_t)bh * NN * DH);
    const char* ksp = (const char*)(ks_g + (size_t)bh * NN * DH);
    const char* vbp = (const char*)(vbT_g + (size_t)bh * DH * NN);
    const char* vsp = (const char*)(vsT_g + (size_t)bh * DH * NN);

    auto load_tile = [&](int t, int buf) {
        int ks0 = t * 64;
        uint32_t base = smb + (uint32_t)buf * (SETU * 4);
        #pragma unroll
        for (int i = 0; i < 4; ++i) {
            int idx = i * 128 + tid;
            int r = idx >> 3, c = idx & 7;
            uint32_t doff = (uint32_t)(r * AW + c * 4) * 4;
            CP_ASYNC16(base + doff,         kbp + (size_t)(ks0 + r) * 128 + c * 16);
            CP_ASYNC16(base + 9216 + doff,  ksp + (size_t)(ks0 + r) * 128 + c * 16);
            CP_ASYNC16(base + 18432 + doff, vbp + (size_t)r * (NN * 2) + ks0 * 2 + c * 16);
            CP_ASYNC16(base + 27648 + doff, vsp + (size_t)r * (NN * 2) + ks0 * 2 + c * 16);
        }
    };

    int ntile = qt + 1;
    load_tile(0, 0);
    CP_COMMIT();
    for (int t = 0; t < ntile; ++t) {
        int buf = t & 1;
        if (t + 1 < ntile) {
            load_tile(t + 1, buf ^ 1);
            CP_COMMIT();
            CP_WAIT(1);
        } else {
            CP_WAIT(0);
        }
        __syncthreads();
        uint32_t kbBase = smb + (uint32_t)buf * (SETU * 4) + lmo;
        int ks0 = t * 64;

        // S = Q K^T (bf16x3, B-fragments via ldmatrix)
        float acc_s[8][4];
        #pragma unroll
        for (int nt = 0; nt < 8; ++nt)
            #pragma unroll
            for (int q = 0; q < 4; ++q) acc_s[nt][q] = 0.f;
        #pragma unroll
        for (int nt = 0; nt < 8; ++nt) {
            uint32_t a0 = kbBase + (uint32_t)(nt * 8 * AW) * 4;
            uint32_t kbf[8], ksf[8];
            LDSM_X4(kbf[0], kbf[1], kbf[2], kbf[3], a0);
            LDSM_X4(kbf[4], kbf[5], kbf[6], kbf[7], a0 + 64);
            LDSM_X4(ksf[0], ksf[1], ksf[2], ksf[3], a0 + 9216);
            LDSM_X4(ksf[4], ksf[5], ksf[6], ksf[7], a0 + 9216 + 64);
            #pragma unroll
            for (int ks = 0; ks < 4; ++ks) {
                mma_bf16(acc_s[nt], qbf[ks], &kbf[2 * ks]);
                mma_bf16(acc_s[nt], qsf[ks], &kbf[2 * ks]);
                mma_bf16(acc_s[nt], qbf[ks], &ksf[2 * ks]);
            }
        }

        // bias + causal mask
        #pragma unroll
        for (int nt = 0; nt < 8; ++nt) {
            int jg = ks0 + nt * 8 + lm * 2;
            acc_s[nt][0] = (jg     <= ig0) ? acc_s[nt][0] - slope * (float)(ig0 - jg)     : -1e30f;
            acc_s[nt][1] = (jg + 1 <= ig0) ? acc_s[nt][1] - slope * (float)(ig0 - jg - 1) : -1e30f;
            acc_s[nt][2] = (jg     <= ig1) ? acc_s[nt][2] - slope * (float)(ig1 - jg)     : -1e30f;
            acc_s[nt][3] = (jg + 1 <= ig1) ? acc_s[nt][3] - slope * (float)(ig1 - jg - 1) : -1e30f;
        }

        // online softmax (quad reduce)
        float rm0 = -1e30f, rm1 = -1e30f;
        #pragma unroll
        for (int nt = 0; nt < 8; ++nt) {
            rm0 = fmaxf(rm0, fmaxf(acc_s[nt][0], acc_s[nt][1]));
            rm1 = fmaxf(rm1, fmaxf(acc_s[nt][2], acc_s[nt][3]));
        }
        rm0 = fmaxf(rm0, __shfl_xor_sync(0xffffffffu, rm0, 1));
        rm0 = fmaxf(rm0, __shfl_xor_sync(0xffffffffu, rm0, 2));
        rm1 = fmaxf(rm1, __shfl_xor_sync(0xffffffffu, rm1, 1));
        rm1 = fmaxf(rm1, __shfl_xor_sync(0xffffffffu, rm1, 2));
        float mn0 = fmaxf(m0r, rm0), mn1 = fmaxf(m1r, rm1);
        float al0 = __expf(m0r - mn0), al1 = __expf(m1r - mn1);
        float ls0 = 0.f, ls1 = 0.f;
        #pragma unroll
        for (int nt = 0; nt < 8; ++nt) {
            acc_s[nt][0] = __expf(acc_s[nt][0] - mn0);
            acc_s[nt][1] = __expf(acc_s[nt][1] - mn0);
            acc_s[nt][2] = __expf(acc_s[nt][2] - mn1);
            acc_s[nt][3] = __expf(acc_s[nt][3] - mn1);
            ls0 += acc_s[nt][0] + acc_s[nt][1];
            ls1 += acc_s[nt][2] + acc_s[nt][3];
        }
        ls0 += __shfl_xor_sync(0xffffffffu, ls0, 1);
        ls0 += __shfl_xor_sync(0xffffffffu, ls0, 2);
        ls1 += __shfl_xor_sync(0xffffffffu, ls1, 1);
        ls1 += __shfl_xor_sync(0xffffffffu, ls1, 2);
        l0r = l0r * al0 + ls0;  m0r = mn0;
        l1r = l1r * al1 + ls1;  m1r = mn1;
        #pragma unroll
        for (int nt = 0; nt < 8; ++nt) {
            acc_o[nt][0] *= al0; acc_o[nt][1] *= al0;
            acc_o[nt][2] *= al1; acc_o[nt][3] *= al1;
        }

        // P fragments in-register (S C-fragment == PV A-fragment)
        uint32_t pa[4][4], psa[4][4];
        #pragma unroll
        for (int ks = 0; ks < 4; ++ks) {
            split2(acc_s[2*ks][0],   acc_s[2*ks][1],   pa[ks][0], psa[ks][0]);
            split2(acc_s[2*ks][2],   acc_s[2*ks][3],   pa[ks][1], psa[ks][1]);
            split2(acc_s[2*ks+1][0], acc_s[2*ks+1][1], pa[ks][2], psa[ks][2]);
            split2(acc_s[2*ks+1][2], acc_s[2*ks+1][3], pa[ks][3], psa[ks][3]);
        }

        // O += P @ V (bf16x3, V fragments via ldmatrix)
        uint32_t vbBase = kbBase + 18432;
        #pragma unroll
        for (int nt = 0; nt < 8; ++nt) {
            uint32_t a0 = vbBase + (uint32_t)(nt * 8 * AW) * 4;
            uint32_t vbf[8], vsf[8];
            LDSM_X4(vbf[0], vbf[1], vbf[2], vbf[3], a0);
            LDSM_X4(vbf[4], vbf[5], vbf[6], vbf[7], a0 + 64);
            LDSM_X4(vsf[0], vsf[1], vsf[2], vsf[3], a0 + 9216);
            LDSM_X4(vsf[4], vsf[5], vsf[6], vsf[7], a0 + 9216 + 64);
            #pragma unroll
            for (int ks = 0; ks < 4; ++ks) {
                mma_bf16(acc_o[nt], pa[ks],  &vbf[2 * ks]);
                mma_bf16(acc_o[nt], psa[ks], &vbf[2 * ks]);
                mma_bf16(acc_o[nt], pa[ks],  &vsf[2 * ks]);
            }
        }
        __syncthreads();
    }

    // normalize, split, write packed pairs
    float inv0 = 1.f / l0r, inv1 = 1.f / l1r;
    uint32_t* obu = (uint32_t*)ob_g;
    uint32_t* osu = (uint32_t*)os_g;
    size_t base0 = (((size_t)b * NN + r0) * INNER + h * DH) >> 1;
    size_t base1 = (((size_t)b * NN + r0 + 8) * INNER + h * DH) >> 1;
    #pragma unroll
    for (int nt = 0; nt < 8; ++nt) {
        uint32_t pb, ps;
        split2(acc_o[nt][0] * inv0, acc_o[nt][1] * inv0, pb, ps);
        obu[base0 + nt * 4 + lm] = pb;
        osu[base0 + nt * 4 + lm] = ps;
        split2(acc_o[nt][2] * inv1, acc_o[nt][3] * inv1, pb, ps);
        obu[base1 + nt * 4 + lm] = pb;
        osu[base1 + nt * 4 + lm] = ps;
    }
}

extern "C" void kernel_launch(void* const* d_in, const int* in_sizes, int n_in,
                              void* d_out, int out_size) {
    const float* x     = (const float*)d_in[0];
    const float* gamma = (const float*)d_in[1];
    const float* beta  = (const float*)d_in[2];
    const float* wq1   = (const float*)d_in[3];
    const float* wqd   = (const float*)d_in[4];
    const float* wk1   = (const float*)d_in[5];
    const float* wkd   = (const float*)d_in[6];
    const float* wv1   = (const float*)d_in[7];
    const float* wvd   = (const float*)d_in[8];
    const float* wout  = (const float*)d_in[9];
    float* out = (float*)d_out;

    float* lin;
    __nv_bfloat16 *xnb, *xns, *wb, *ws, *qb, *qs, *kb, *ks, *vbT, *vsT, *ob, *os;
    cudaGetSymbolAddress((void**)&lin, g_lin);
    cudaGetSymbolAddress((void**)&xnb, g_xnb);  cudaGetSymbolAddress((void**)&xns, g_xns);
    cudaGetSymbolAddress((void**)&wb,  g_wb);   cudaGetSymbolAddress((void**)&ws,  g_ws);
    cudaGetSymbolAddress((void**)&qb,  g_qb);   cudaGetSymbolAddress((void**)&qs,  g_qs);
    cudaGetSymbolAddress((void**)&kb,  g_kb);   cudaGetSymbolAddress((void**)&ks,  g_ks);
    cudaGetSymbolAddress((void**)&vbT, g_vbT);  cudaGetSymbolAddress((void**)&vsT, g_vsT);
    cudaGetSymbolAddress((void**)&ob,  g_ob);   cudaGetSymbolAddress((void**)&os,  g_os);

    cudaFuncSetAttribute(gemm_bf16, cudaFuncAttributeMaxDynamicSharedMemorySize, SM_GEMM);
    cudaFuncSetAttribute(attn_kernel, cudaFuncAttributeMaxDynamicSharedMemorySize, SMEM_ATTN);

    // 1) LayerNorm (split bf16 out) + weight split
    ln_kernel<<<ROWS, 256>>>(x, gamma, beta, xnb, xns);
    wsplit_kernel<<<WSZ / 256, 256>>>(wq1, wk1, wv1, wout, wb, ws);

    // 2) q/k/v pointwise projections (bf16x3, one launch, z=3) -> lin fp32
    dim3 g1(4, 32, 3);
    gemm_bf16<<<g1, 256, SM_GEMM>>>(xnb, xns, wb, ws, WSZ, lin, (size_t)ROWS * INNER);

    // 3) depthwise conv + split (q/k d-major, v transposed n-major)
    conv_qk<<<(ROWS * INNER / 4) / 256, 256>>>(lin, wqd, wkd, qb, qs, kb, ks);
    conv_v<<<dim3(NN / 32, INNER / 32, BB), 256>>>(lin + 2 * (size_t)ROWS * INNER, wvd, vbT, vsT);

    // 4) flash attention (bf16x3, ldmatrix, prefetched) -> split bf16 out
    attn_kernel<<<dim3(NN / 64, BB * HH), 128, SMEM_ATTN>>>(qb, qs, kb, ks, vbT, vsT, ob, os);

    // 5) output projection (bf16x3) straight into d_out
    dim3 g2(4, 32, 1);
    gemm_bf16<<<g2, 256, SM_GEMM>>>(ob, os, wb + 3 * WSZ, ws + 3 * WSZ, 0, out, 0);
}

// round 12
// speedup vs baseline: 1.2265x; 1.2265x over previous
#include <cuda_runtime.h>
#include <cuda_bf16.h>
#include <cuda_fp16.h>
#include <math.h>
#include <stdint.h>

#define BB 2
#define NN 2048
#define DD 512
#define HH 8
#define DH 64
#define INNER 512
#define ROWS (BB*NN)            // 4096
#define BHN ((size_t)BB*HH*NN*DH)
#define WSZ (INNER*DD)          // 262144 = 2^18

// -------- scratch (device globals; no allocation allowed) --------
__device__ float g_lin[3*ROWS*INNER];          // pointwise-conv outputs (fp32)
__device__ __nv_bfloat16 g_xnb[ROWS*DD];       // LN out, big
__device__ __nv_bfloat16 g_xns[ROWS*DD];       // LN out, small
__device__ __nv_bfloat16 g_wb[4*WSZ];          // wq1,wk1,wv1,wout big
__device__ __nv_bfloat16 g_ws[4*WSZ];          // small
__device__ __nv_bfloat16 g_qb[BHN], g_qs[BHN]; // q split, [b][h][n][d]
__device__ __nv_bfloat16 g_kb[BHN], g_ks[BHN]; // k split, [b][h][n][d]
__device__ __half g_vhT[BHN];                  // v fp16, TRANSPOSED [b][h][d][n]
__device__ __nv_bfloat16 g_ob[ROWS*INNER], g_os[ROWS*INNER]; // attn out split

// ---------------- helpers ----------------
__device__ __forceinline__ uint32_t smem_u32(const void* p) {
    uint32_t a;
    asm("{ .reg .u64 t; cvta.to.shared.u64 t, %1; cvt.u32.u64 %0, t; }" : "=r"(a) : "l"(p));
    return a;
}
__device__ __forceinline__ void mma_bf16(float* c, const uint32_t* a, const uint32_t* b) {
    asm volatile(
        "mma.sync.aligned.m16n8k16.row.col.f32.bf16.bf16.f32 "
        "{%0,%1,%2,%3}, {%4,%5,%6,%7}, {%8,%9}, {%0,%1,%2,%3};"
        : "+f"(c[0]), "+f"(c[1]), "+f"(c[2]), "+f"(c[3])
        : "r"(a[0]), "r"(a[1]), "r"(a[2]), "r"(a[3]), "r"(b[0]), "r"(b[1]));
}
__device__ __forceinline__ void mma_fp16(float* c, const uint32_t* a, const uint32_t* b) {
    asm volatile(
        "mma.sync.aligned.m16n8k16.row.col.f32.f16.f16.f32 "
        "{%0,%1,%2,%3}, {%4,%5,%6,%7}, {%8,%9}, {%0,%1,%2,%3};"
        : "+f"(c[0]), "+f"(c[1]), "+f"(c[2]), "+f"(c[3])
        : "r"(a[0]), "r"(a[1]), "r"(a[2]), "r"(a[3]), "r"(b[0]), "r"(b[1]));
}
__device__ __forceinline__ void split1(float x, __nv_bfloat16& b, __nv_bfloat16& s) {
    b = __float2bfloat16(x);
    s = __float2bfloat16(x - __bfloat162float(b));
}
__device__ __forceinline__ void split2(float x0, float x1, uint32_t& b, uint32_t& s) {
    __nv_bfloat162 tb = __float22bfloat162_rn(make_float2(x0, x1));
    float2 tf = __bfloat1622float2(tb);
    __nv_bfloat162 ts = __float22bfloat162_rn(make_float2(x0 - tf.x, x1 - tf.y));
    b = *reinterpret_cast<uint32_t*>(&tb);
    s = *reinterpret_cast<uint32_t*>(&ts);
}
__device__ __forceinline__ uint32_t pack_h2(float x0, float x1) {
    __half2 h = __float22half2_rn(make_float2(x0, x1));
    return *reinterpret_cast<uint32_t*>(&h);
}
#define CP_ASYNC16(dst, src) \
    asm volatile("cp.async.cg.shared.global [%0], [%1], 16;" :: "r"(dst), "l"(src) : "memory")
#define CP_COMMIT() asm volatile("cp.async.commit_group;" ::: "memory")
#define CP_WAIT(n)  asm volatile("cp.async.wait_group %0;" :: "n"(n) : "memory")

// ---------------- LayerNorm -> split bf16 ----------------
__global__ void ln_kernel(const float* __restrict__ x,
                          const float* __restrict__ gamma,
                          const float* __restrict__ beta,
                          __nv_bfloat16* __restrict__ xnb,
                          __nv_bfloat16* __restrict__ xns) {
    int row = blockIdx.x;
    const float* xr = x + (size_t)row * DD;
    int t = threadIdx.x;
    float v0 = xr[t], v1 = xr[t + 256];
    float s = v0 + v1;
    float sq = v0 * v0 + v1 * v1;
    #pragma unroll
    for (int o = 16; o > 0; o >>= 1) {
        s  += __shfl_xor_sync(0xffffffffu, s, o);
        sq += __shfl_xor_sync(0xffffffffu, sq, o);
    }
    __shared__ float ss[8], ssq[8];
    if ((t & 31) == 0) { ss[t >> 5] = s; ssq[t >> 5] = sq; }
    __syncthreads();
    s = 0.f; sq = 0.f;
    #pragma unroll
    for (int i = 0; i < 8; ++i) { s += ss[i]; sq += ssq[i]; }
    float mean = s * (1.f / DD);
    float var  = sq * (1.f / DD) - mean * mean;
    float rstd = rsqrtf(var + 1e-5f);
    float y0 = (v0 - mean) * rstd * gamma[t]       + beta[t];
    float y1 = (v1 - mean) * rstd * gamma[t + 256] + beta[t + 256];
    __nv_bfloat16 b, sm;
    split1(y0, b, sm); xnb[(size_t)row * DD + t] = b;       xns[(size_t)row * DD + t] = sm;
    split1(y1, b, sm); xnb[(size_t)row * DD + t + 256] = b; xns[(size_t)row * DD + t + 256] = sm;
}

// ---------------- weight split (vectorized) ----------------
__global__ void wsplit_kernel(const float* __restrict__ wq1, const float* __restrict__ wk1,
                              const float* __restrict__ wv1, const float* __restrict__ wout,
                              __nv_bfloat16* __restrict__ wb, __nv_bfloat16* __restrict__ ws) {
    int idx = blockIdx.x * 256 + threadIdx.x;       // over 4*WSZ/4
    int sel = idx >> 16;
    int off = idx & 65535;
    const float* src = (sel == 0) ? wq1 : (sel == 1) ? wk1 : (sel == 2) ? wv1 : wout;
    float4 v = ((const float4*)src)[off];
    uint32_t b01, s01, b23, s23;
    split2(v.x, v.y, b01, s01);
    split2(v.z, v.w, b23, s23);
    ((uint2*)wb)[idx] = make_uint2(b01, b23);
    ((uint2*)ws)[idx] = make_uint2(s01, s23);
}

// ---------------- bf16x3 mma.sync GEMM (R9 version) ----------------
#define GW 20
#define GTB (128 * GW * 4)
#define SM_GEMM (2 * 4 * GTB)

__global__ void __launch_bounds__(256)
gemm_bf16(const __nv_bfloat16* __restrict__ Abig, const __nv_bfloat16* __restrict__ Asml,
          const __nv_bfloat16* __restrict__ wb,   const __nv_bfloat16* __restrict__ ws,
          size_t w_stride, float* __restrict__ Cbase, size_t c_stride) {
    const __nv_bfloat16* Wb = wb + blockIdx.z * w_stride;
    const __nv_bfloat16* Ws = ws + blockIdx.z * w_stride;
    float* C = Cbase + blockIdx.z * c_stride;

    extern __shared__ char smc[];
    uint32_t smb = smem_u32(smc);
    int tid = threadIdx.x;
    int wid = tid >> 5, lane = tid & 31;
    int wm = wid >> 2, wn = wid & 3;
    int lq = lane >> 2, lm = lane & 3;
    int m0 = blockIdx.y * 128, e0 = blockIdx.x * 128;

    int lrow = tid >> 1;
    int lc2  = (tid & 1) * 2;

    float acc[4][4][4];
    #pragma unroll
    for (int i = 0; i < 4; ++i)
        #pragma unroll
        for (int j = 0; j < 4; ++j)
            #pragma unroll
            for (int q = 0; q < 4; ++q) acc[i][j][q] = 0.f;

    auto load_chunk = [&](int c, int buf) {
        int k0 = c << 5;
        uint32_t base = smb + buf * 4 * GTB;
        const __nv_bfloat16* a0 = Abig + (size_t)(m0 + lrow) * 512 + k0;
        const __nv_bfloat16* a1 = Asml + (size_t)(m0 + lrow) * 512 + k0;
        const __nv_bfloat16* w0 = Wb + (size_t)(e0 + lrow) * 512 + k0;
        const __nv_bfloat16* w1 = Ws + (size_t)(e0 + lrow) * 512 + k0;
        #pragma unroll
        for (int j = 0; j < 2; ++j) {
            int c4 = lc2 + j;
            uint32_t doff = (uint32_t)(lrow * GW + c4 * 4) * 4;
            CP_ASYNC16(base + doff,             a0 + c4 * 8);
            CP_ASYNC16(base + GTB + doff,       a1 + c4 * 8);
            CP_ASYNC16(base + 2 * GTB + doff,   w0 + c4 * 8);
            CP_ASYNC16(base + 3 * GTB + doff,   w1 + c4 * 8);
        }
    };

    load_chunk(0, 0);
    CP_COMMIT();

    const uint32_t* smu = (const uint32_t*)smc;
    for (int c = 0; c < 16; ++c) {
        if (c + 1 < 16) {
            load_chunk(c + 1, (c + 1) & 1);
            CP_COMMIT();
            CP_WAIT(1);
        } else {
            CP_WAIT(0);
        }
        __syncthreads();
        const uint32_t* Abu = smu + (c & 1) * 4 * (GTB / 4);
        const uint32_t* Asu = Abu + GTB / 4;
        const uint32_t* Wbu = Abu + 2 * (GTB / 4);
        const uint32_t* Wsu = Abu + 3 * (GTB / 4);
        #pragma unroll
        for (int ks = 0; ks < 2; ++ks) {
            int kb = ks * 8;
            uint32_t ab[4][4], as_[4][4], bb[4][2], bs[4][2];
            #pragma unroll
            for (int mt = 0; mt < 4; ++mt) {
                int r = wm * 64 + mt * 16 + lq;
                ab[mt][0] = Abu[r * GW + kb + lm];
                ab[mt][1] = Abu[(r + 8) * GW + kb + lm];
                ab[mt][2] = Abu[r * GW + kb + lm + 4];
                ab[mt][3] = Abu[(r + 8) * GW + kb + lm + 4];
                as_[mt][0] = Asu[r * GW + kb + lm];
                as_[mt][1] = Asu[(r + 8) * GW + kb + lm];
                as_[mt][2] = Asu[r * GW + kb + lm + 4];
                as_[mt][3] = Asu[(r + 8) * GW + kb + lm + 4];
            }
            #pragma unroll
            for (int nt = 0; nt < 4; ++nt) {
                int n = wn * 32 + nt * 8 + lq;
                bb[nt][0] = Wbu[n * GW + kb + lm];
                bb[nt][1] = Wbu[n * GW + kb + lm + 4];
                bs[nt][0] = Wsu[n * GW + kb + lm];
                bs[nt][1] = Wsu[n * GW + kb + lm + 4];
            }
            #pragma unroll
            for (int mt = 0; mt < 4; ++mt)
                #pragma unroll
                for (int nt = 0; nt < 4; ++nt) {
                    mma_bf16(acc[mt][nt], ab[mt],  bb[nt]);
                    mma_bf16(acc[mt][nt], as_[mt], bb[nt]);
                    mma_bf16(acc[mt][nt], ab[mt],  bs[nt]);
                }
        }
        __syncthreads();
    }

    #pragma unroll
    for (int mt = 0; mt < 4; ++mt) {
        int r0 = m0 + wm * 64 + mt * 16 + lq;
        #pragma unroll
        for (int nt = 0; nt < 4; ++nt) {
            int c0 = e0 + wn * 32 + nt * 8 + lm * 2;
            *(float2*)(C + (size_t)r0 * 512 + c0)       = make_float2(acc[mt][nt][0], acc[mt][nt][1]);
            *(float2*)(C + (size_t)(r0 + 8) * 512 + c0) = make_float2(acc[mt][nt][2], acc[mt][nt][3]);
        }
    }
}

// ------- depthwise conv q,k (vectorized float4) + split -------
__global__ void conv_qk(const float* __restrict__ lin,
                        const float* __restrict__ wqd, const float* __restrict__ wkd,
                        __nv_bfloat16* __restrict__ qb, __nv_bfloat16* __restrict__ qs,
                        __nv_bfloat16* __restrict__ kb, __nv_bfloat16* __restrict__ ks) {
    int idx = blockIdx.x * 256 + threadIdx.x;      // over ROWS*INNER/4
    int e4 = idx & 127;
    int n  = (idx >> 7) & (NN - 1);
    int b  = idx >> 18;
    int e  = e4 << 2;
    int h = e >> 6, d = e & 63;
    size_t dstu2 = ((((size_t)(b * HH + h) * NN + n) * DH + d)) >> 2;
    const float4* L4 = (const float4*)lin;
    const float4 z4 = make_float4(0.f, 0.f, 0.f, 0.f);
    #pragma unroll
    for (int t = 0; t < 2; ++t) {
        const float4* L = L4 + (size_t)t * (ROWS * INNER / 4);
        const float* wd = t ? wkd : wqd;
        float4 y2 = L[idx];
        float4 y1 = (n >= 1) ? L[idx - 128] : z4;
        float4 y0 = (n >= 2) ? L[idx - 256] : z4;
        float v[4];
        v[0] = wd[e*3+0]*y0.x + wd[e*3+1]*y1.x + wd[e*3+2]*y2.x;
        v[1] = wd[e*3+3]*y0.y + wd[e*3+4]*y1.y + wd[e*3+5]*y2.y;
        v[2] = wd[e*3+6]*y0.z + wd[e*3+7]*y1.z + wd[e*3+8]*y2.z;
        v[3] = wd[e*3+9]*y0.w + wd[e*3+10]*y1.w + wd[e*3+11]*y2.w;
        if (t == 0) { v[0] *= 0.125f; v[1] *= 0.125f; v[2] *= 0.125f; v[3] *= 0.125f; }
        uint32_t b01, s01, b23, s23;
        split2(v[0], v[1], b01, s01);
        split2(v[2], v[3], b23, s23);
        if (t == 0) {
            ((uint2*)qb)[dstu2] = make_uint2(b01, b23);
            ((uint2*)qs)[dstu2] = make_uint2(s01, s23);
        } else {
            ((uint2*)kb)[dstu2] = make_uint2(b01, b23);
            ((uint2*)ks)[dstu2] = make_uint2(s01, s23);
        }
    }
}

// ------- depthwise conv for v + TRANSPOSED fp16 output -------
__global__ void conv_v(const float* __restrict__ lin2, const float* __restrict__ wvd,
                       __half* __restrict__ vhT) {
    __shared__ float tile[34 * 33];
    int b = blockIdx.z, e0 = blockIdx.y * 32, n0 = blockIdx.x * 32;
    int tid = threadIdx.x;
    for (int i = tid; i < 34 * 32; i += 256) {
        int r = i >> 5, c = i & 31;
        int n = n0 - 2 + r;
        tile[r * 33 + c] = (n >= 0) ? lin2[((size_t)b * NN + n) * INNER + e0 + c] : 0.f;
    }
    __syncthreads();
    int nl = tid & 31;
    #pragma unroll
    for (int p = 0; p < 4; ++p) {
        int el = (tid >> 5) + p * 8;
        int eg = e0 + el;
        int h = eg >> 6, d = eg & 63;
        float y0 = tile[nl * 33 + el];
        float y1 = tile[(nl + 1) * 33 + el];
        float y2 = tile[(nl + 2) * 33 + el];
        float v = wvd[eg * 3 + 0] * y0 + wvd[eg * 3 + 1] * y1 + wvd[eg * 3 + 2] * y2;
        size_t dst = ((size_t)(b * HH + h) * DH + d) * NN + n0 + nl;
        vhT[dst] = __float2half_rn(v);
    }
}

// ---- Flash attention: S bf16x3, PV fp16 single-pass, prefetch ----
// Br=Bc=64, 128 threads (4 warps x 16 rows). Double-buffered K/V tiles.
#define AW 36
#define SETU (3 * 64 * AW)              // u32 per buffer set (Kb,Ks,Vh)
#define SMEM_ATTN (2 * SETU * 4)        // 55296 B -> 3 blocks/SM

__global__ void __launch_bounds__(128, 3)
attn_kernel(const __nv_bfloat16* __restrict__ qb_g, const __nv_bfloat16* __restrict__ qs_g,
            const __nv_bfloat16* __restrict__ kb_g, const __nv_bfloat16* __restrict__ ks_g,
            const __half* __restrict__ vhT_g,
            __nv_bfloat16* __restrict__ ob_g, __nv_bfloat16* __restrict__ os_g) {
    extern __shared__ uint32_t smu[];
    uint32_t smb = smem_u32(smu);

    int qt = gridDim.x - 1 - blockIdx.x;   // big tiles first
    int bh = blockIdx.y;
    int b = bh >> 3, h = bh & 7;
    int qs0 = qt * 64;

    int tid = threadIdx.x;
    int wid = tid >> 5, lane = tid & 31;
    int lq = lane >> 2, lm = lane & 3;
    int wr = wid * 16;

    // Q fragments direct from global (packed u32 = 2 bf16 over d)
    const uint32_t* qbu = (const uint32_t*)qb_g + (size_t)bh * NN * 32;
    const uint32_t* qsu = (const uint32_t*)qs_g + (size_t)bh * NN * 32;
    int r0 = qs0 + wr + lq;
    uint32_t qbf[4][4], qsf[4][4];
    #pragma unroll
    for (int ks = 0; ks < 4; ++ks) {
        qbf[ks][0] = qbu[(size_t)r0 * 32 + ks * 8 + lm];
        qbf[ks][1] = qbu[(size_t)(r0 + 8) * 32 + ks * 8 + lm];
        qbf[ks][2] = qbu[(size_t)r0 * 32 + ks * 8 + lm + 4];
        qbf[ks][3] = qbu[(size_t)(r0 + 8) * 32 + ks * 8 + lm + 4];
        qsf[ks][0] = qsu[(size_t)r0 * 32 + ks * 8 + lm];
        qsf[ks][1] = qsu[(size_t)(r0 + 8) * 32 + ks * 8 + lm];
        qsf[ks][2] = qsu[(size_t)r0 * 32 + ks * 8 + lm + 4];
        qsf[ks][3] = qsu[(size_t)(r0 + 8) * 32 + ks * 8 + lm + 4];
    }

    float acc_o[8][4];
    #pragma unroll
    for (int nt = 0; nt < 8; ++nt)
        #pragma unroll
        for (int q = 0; q < 4; ++q) acc_o[nt][q] = 0.f;
    float m0r = -1e30f, m1r = -1e30f, l0r = 0.f, l1r = 0.f;
    float slope = exp2f(-(float)(h + 1));
    int ig0 = r0, ig1 = r0 + 8;

    const char* kbp = (const char*)(kb_g + (size_t)bh * NN * DH);
    const char* ksp = (const char*)(ks_g + (size_t)bh * NN * DH);
    const char* vhp = (const char*)(vhT_g + (size_t)bh * DH * NN);

    auto load_tile = [&](int t, int buf) {
        int ks0 = t * 64;
        uint32_t base = smb + (uint32_t)buf * (SETU * 4);
        #pragma unroll
        for (int i = 0; i < 4; ++i) {
            int idx = i * 128 + tid;
            int r = idx >> 3, c = idx & 7;
            uint32_t doff = (uint32_t)(r * AW + c * 4) * 4;
            CP_ASYNC16(base + doff,         kbp + (size_t)(ks0 + r) * 128 + c * 16);
            CP_ASYNC16(base + 9216 + doff,  ksp + (size_t)(ks0 + r) * 128 + c * 16);
            CP_ASYNC16(base + 18432 + doff, vhp + (size_t)r * (NN * 2) + ks0 * 2 + c * 16);
        }
    };

    int ntile = qt + 1;
    load_tile(0, 0);
    CP_COMMIT();
    for (int t = 0; t < ntile; ++t) {
        int buf = t & 1;
        if (t + 1 < ntile) {
            load_tile(t + 1, buf ^ 1);
            CP_COMMIT();
            CP_WAIT(1);
        } else {
            CP_WAIT(0);
        }
        __syncthreads();
        const uint32_t* Kb = smu + buf * SETU;
        const uint32_t* Ks = Kb + 2304;
        const uint32_t* Vh = Kb + 4608;
        int ks0 = t * 64;

        // S = Q K^T (bf16x3, 4 k16-steps)
        float acc_s[8][4];
        #pragma unroll
        for (int nt = 0; nt < 8; ++nt)
            #pragma unroll
            for (int q = 0; q < 4; ++q) acc_s[nt][q] = 0.f;
        #pragma unroll
        for (int ks = 0; ks < 4; ++ks) {
            int kc = ks * 8;
            #pragma unroll
            for (int nt = 0; nt < 8; ++nt) {
                int rb = (nt * 8 + lq) * AW + kc + lm;
                uint32_t bb[2], bs[2];
                bb[0] = Kb[rb];     bb[1] = Kb[rb + 4];
                bs[0] = Ks[rb];     bs[1] = Ks[rb + 4];
                mma_bf16(acc_s[nt], qbf[ks], bb);
                mma_bf16(acc_s[nt], qsf[ks], bb);
                mma_bf16(acc_s[nt], qbf[ks], bs);
            }
        }

        // bias + causal mask
        #pragma unroll
        for (int nt = 0; nt < 8; ++nt) {
            int jg = ks0 + nt * 8 + lm * 2;
            acc_s[nt][0] = (jg     <= ig0) ? acc_s[nt][0] - slope * (float)(ig0 - jg)     : -1e30f;
            acc_s[nt][1] = (jg + 1 <= ig0) ? acc_s[nt][1] - slope * (float)(ig0 - jg - 1) : -1e30f;
            acc_s[nt][2] = (jg     <= ig1) ? acc_s[nt][2] - slope * (float)(ig1 - jg)     : -1e30f;
            acc_s[nt][3] = (jg + 1 <= ig1) ? acc_s[nt][3] - slope * (float)(ig1 - jg - 1) : -1e30f;
        }

        // online softmax (quad reduce)
        float rm0 = -1e30f, rm1 = -1e30f;
        #pragma unroll
        for (int nt = 0; nt < 8; ++nt) {
            rm0 = fmaxf(rm0, fmaxf(acc_s[nt][0], acc_s[nt][1]));
            rm1 = fmaxf(rm1, fmaxf(acc_s[nt][2], acc_s[nt][3]));
        }
        rm0 = fmaxf(rm0, __shfl_xor_sync(0xffffffffu, rm0, 1));
        rm0 = fmaxf(rm0, __shfl_xor_sync(0xffffffffu, rm0, 2));
        rm1 = fmaxf(rm1, __shfl_xor_sync(0xffffffffu, rm1, 1));
        rm1 = fmaxf(rm1, __shfl_xor_sync(0xffffffffu, rm1, 2));
        float mn0 = fmaxf(m0r, rm0), mn1 = fmaxf(m1r, rm1);
        float al0 = __expf(m0r - mn0), al1 = __expf(m1r - mn1);
        float ls0 = 0.f, ls1 = 0.f;
        #pragma unroll
        for (int nt = 0; nt < 8; ++nt) {
            acc_s[nt][0] = __expf(acc_s[nt][0] - mn0);
            acc_s[nt][1] = __expf(acc_s[nt][1] - mn0);
            acc_s[nt][2] = __expf(acc_s[nt][2] - mn1);
            acc_s[nt][3] = __expf(acc_s[nt][3] - mn1);
            ls0 += acc_s[nt][0] + acc_s[nt][1];
            ls1 += acc_s[nt][2] + acc_s[nt][3];
        }
        ls0 += __shfl_xor_sync(0xffffffffu, ls0, 1);
        ls0 += __shfl_xor_sync(0xffffffffu, ls0, 2);
        ls1 += __shfl_xor_sync(0xffffffffu, ls1, 1);
        ls1 += __shfl_xor_sync(0xffffffffu, ls1, 2);
        l0r = l0r * al0 + ls0;  m0r = mn0;
        l1r = l1r * al1 + ls1;  m1r = mn1;
        #pragma unroll
        for (int nt = 0; nt < 8; ++nt) {
            acc_o[nt][0] *= al0; acc_o[nt][1] *= al0;
            acc_o[nt][2] *= al1; acc_o[nt][3] *= al1;
        }

        // O += P @ V : single-pass fp16 (P rounded rn to fp16 in-register)
        #pragma unroll
        for (int ks = 0; ks < 4; ++ks) {
            uint32_t pa[4];
            pa[0] = pack_h2(acc_s[2*ks][0],   acc_s[2*ks][1]);
            pa[1] = pack_h2(acc_s[2*ks][2],   acc_s[2*ks][3]);
            pa[2] = pack_h2(acc_s[2*ks+1][0], acc_s[2*ks+1][1]);
            pa[3] = pack_h2(acc_s[2*ks+1][2], acc_s[2*ks+1][3]);
            int kc = ks * 8;
            #pragma unroll
            for (int nt = 0; nt < 8; ++nt) {
                int rb = (nt * 8 + lq) * AW + kc + lm;
                uint32_t vh_[2];
                vh_[0] = Vh[rb];     vh_[1] = Vh[rb + 4];
                mma_fp16(acc_o[nt], pa, vh_);
            }
        }
        __syncthreads();
    }

    // normalize, split, write packed pairs
    float inv0 = 1.f / l0r, inv1 = 1.f / l1r;
    uint32_t* obu = (uint32_t*)ob_g;
    uint32_t* osu = (uint32_t*)os_g;
    size_t base0 = (((size_t)b * NN + r0) * INNER + h * DH) >> 1;
    size_t base1 = (((size_t)b * NN + r0 + 8) * INNER + h * DH) >> 1;
    #pragma unroll
    for (int nt = 0; nt < 8; ++nt) {
        uint32_t pb, ps;
        split2(acc_o[nt][0] * inv0, acc_o[nt][1] * inv0, pb, ps);
        obu[base0 + nt * 4 + lm] = pb;
        osu[base0 + nt * 4 + lm] = ps;
        split2(acc_o[nt][2] * inv1, acc_o[nt][3] * inv1, pb, ps);
        obu[base1 + nt * 4 + lm] = pb;
        osu[base1 + nt * 4 + lm] = ps;
    }
}

extern "C" void kernel_launch(void* const* d_in, const int* in_sizes, int n_in,
                              void* d_out, int out_size) {
    const float* x     = (const float*)d_in[0];
    const float* gamma = (const float*)d_in[1];
    const float* beta  = (const float*)d_in[2];
    const float* wq1   = (const float*)d_in[3];
    const float* wqd   = (const float*)d_in[4];
    const float* wk1   = (const float*)d_in[5];
    const float* wkd   = (const float*)d_in[6];
    const float* wv1   = (const float*)d_in[7];
    const float* wvd   = (const float*)d_in[8];
    const float* wout  = (const float*)d_in[9];
    float* out = (float*)d_out;

    float* lin;
    __half* vhT;
    __nv_bfloat16 *xnb, *xns, *wb, *ws, *qb, *qs, *kb, *ks, *ob, *os;
    cudaGetSymbolAddress((void**)&lin, g_lin);
    cudaGetSymbolAddress((void**)&xnb, g_xnb);  cudaGetSymbolAddress((void**)&xns, g_xns);
    cudaGetSymbolAddress((void**)&wb,  g_wb);   cudaGetSymbolAddress((void**)&ws,  g_ws);
    cudaGetSymbolAddress((void**)&qb,  g_qb);   cudaGetSymbolAddress((void**)&qs,  g_qs);
    cudaGetSymbolAddress((void**)&kb,  g_kb);   cudaGetSymbolAddress((void**)&ks,  g_ks);
    cudaGetSymbolAddress((void**)&vhT, g_vhT);
    cudaGetSymbolAddress((void**)&ob,  g_ob);   cudaGetSymbolAddress((void**)&os,  g_os);

    cudaFuncSetAttribute(gemm_bf16, cudaFuncAttributeMaxDynamicSharedMemorySize, SM_GEMM);
    cudaFuncSetAttribute(attn_kernel, cudaFuncAttributeMaxDynamicSharedMemorySize, SMEM_ATTN);

    // 1) LayerNorm (split bf16 out) + weight split
    ln_kernel<<<ROWS, 256>>>(x, gamma, beta, xnb, xns);
    wsplit_kernel<<<WSZ / 256, 256>>>(wq1, wk1, wv1, wout, wb, ws);

    // 2) q/k/v pointwise projections (bf16x3, one launch, z=3) -> lin fp32
    dim3 g1(4, 32, 3);
    gemm_bf16<<<g1, 256, SM_GEMM>>>(xnb, xns, wb, ws, WSZ, lin, (size_t)ROWS * INNER);

    // 3) depthwise conv + split (q/k d-major bf16, v transposed fp16)
    conv_qk<<<(ROWS * INNER / 4) / 256, 256>>>(lin, wqd, wkd, qb, qs, kb, ks);
    conv_v<<<dim3(NN / 32, INNER / 32, BB), 256>>>(lin + 2 * (size_t)ROWS * INNER, wvd, vhT);

    // 4) flash attention (S bf16x3, PV fp16) -> split bf16 out
    attn_kernel<<<dim3(NN / 64, BB * HH), 128, SMEM_ATTN>>>(qb, qs, kb, ks, vhT, ob, os);

    // 5) output projection (bf16x3) straight into d_out
    dim3 g2(4, 32, 1);
    gemm_bf16<<<g2, 256, SM_GEMM>>>(ob, os, wb + 3 * WSZ, ws + 3 * WSZ, 0, out, 0);
}

// round 13
// speedup vs baseline: 1.3922x; 1.1351x over previous
#include <cuda_runtime.h>
#include <cuda_bf16.h>
#include <cuda_fp16.h>
#include <math.h>
#include <stdint.h>

#define BB 2
#define NN 2048
#define DD 512
#define HH 8
#define DH 64
#define INNER 512
#define ROWS (BB*NN)            // 4096
#define BHN ((size_t)BB*HH*NN*DH)
#define WSZ (INNER*DD)          // 262144 = 2^18

// -------- scratch (device globals; no allocation allowed) --------
__device__ float g_lin[3*ROWS*INNER];          // pointwise-conv outputs (fp32)
__device__ __nv_bfloat16 g_xnb[ROWS*DD];       // LN out, big
__device__ __nv_bfloat16 g_xns[ROWS*DD];       // LN out, small
__device__ __half g_xnh[ROWS*DD];              // LN out, fp16 (for V proj)
__device__ __nv_bfloat16 g_wb[2*WSZ];          // wq1,wk1 big
__device__ __nv_bfloat16 g_ws[2*WSZ];          // wq1,wk1 small
__device__ __half g_wh[2*WSZ];                 // wv1, wout fp16
__device__ __nv_bfloat16 g_qb[BHN], g_qs[BHN]; // q split, [b][h][n][d]
__device__ __nv_bfloat16 g_kb[BHN], g_ks[BHN]; // k split, [b][h][n][d]
__device__ __half g_vhT[BHN];                  // v fp16, TRANSPOSED [b][h][d][n]
__device__ __half g_oh[ROWS*INNER];            // attn out fp16

// ---------------- helpers ----------------
__device__ __forceinline__ uint32_t smem_u32(const void* p) {
    uint32_t a;
    asm("{ .reg .u64 t; cvta.to.shared.u64 t, %1; cvt.u32.u64 %0, t; }" : "=r"(a) : "l"(p));
    return a;
}
__device__ __forceinline__ void mma_bf16(float* c, const uint32_t* a, const uint32_t* b) {
    asm volatile(
        "mma.sync.aligned.m16n8k16.row.col.f32.bf16.bf16.f32 "
        "{%0,%1,%2,%3}, {%4,%5,%6,%7}, {%8,%9}, {%0,%1,%2,%3};"
        : "+f"(c[0]), "+f"(c[1]), "+f"(c[2]), "+f"(c[3])
        : "r"(a[0]), "r"(a[1]), "r"(a[2]), "r"(a[3]), "r"(b[0]), "r"(b[1]));
}
__device__ __forceinline__ void mma_fp16(float* c, const uint32_t* a, const uint32_t* b) {
    asm volatile(
        "mma.sync.aligned.m16n8k16.row.col.f32.f16.f16.f32 "
        "{%0,%1,%2,%3}, {%4,%5,%6,%7}, {%8,%9}, {%0,%1,%2,%3};"
        : "+f"(c[0]), "+f"(c[1]), "+f"(c[2]), "+f"(c[3])
        : "r"(a[0]), "r"(a[1]), "r"(a[2]), "r"(a[3]), "r"(b[0]), "r"(b[1]));
}
__device__ __forceinline__ void split1(float x, __nv_bfloat16& b, __nv_bfloat16& s) {
    b = __float2bfloat16(x);
    s = __float2bfloat16(x - __bfloat162float(b));
}
__device__ __forceinline__ void split2(float x0, float x1, uint32_t& b, uint32_t& s) {
    __nv_bfloat162 tb = __float22bfloat162_rn(make_float2(x0, x1));
    float2 tf = __bfloat1622float2(tb);
    __nv_bfloat162 ts = __float22bfloat162_rn(make_float2(x0 - tf.x, x1 - tf.y));
    b = *reinterpret_cast<uint32_t*>(&tb);
    s = *reinterpret_cast<uint32_t*>(&ts);
}
__device__ __forceinline__ uint32_t pack_h2(float x0, float x1) {
    __half2 h = __float22half2_rn(make_float2(x0, x1));
    return *reinterpret_cast<uint32_t*>(&h);
}
#define CP_ASYNC16(dst, src) \
    asm volatile("cp.async.cg.shared.global [%0], [%1], 16;" :: "r"(dst), "l"(src) : "memory")
#define CP_COMMIT() asm volatile("cp.async.commit_group;" ::: "memory")
#define CP_WAIT(n)  asm volatile("cp.async.wait_group %0;" :: "n"(n) : "memory")

// ---------------- LayerNorm -> split bf16 + fp16 ----------------
__global__ void ln_kernel(const float* __restrict__ x,
                          const float* __restrict__ gamma,
                          const float* __restrict__ beta,
                          __nv_bfloat16* __restrict__ xnb,
                          __nv_bfloat16* __restrict__ xns,
                          __half* __restrict__ xnh) {
    int row = blockIdx.x;
    const float* xr = x + (size_t)row * DD;
    int t = threadIdx.x;
    float v0 = xr[t], v1 = xr[t + 256];
    float s = v0 + v1;
    float sq = v0 * v0 + v1 * v1;
    #pragma unroll
    for (int o = 16; o > 0; o >>= 1) {
        s  += __shfl_xor_sync(0xffffffffu, s, o);
        sq += __shfl_xor_sync(0xffffffffu, sq, o);
    }
    __shared__ float ss[8], ssq[8];
    if ((t & 31) == 0) { ss[t >> 5] = s; ssq[t >> 5] = sq; }
    __syncthreads();
    s = 0.f; sq = 0.f;
    #pragma unroll
    for (int i = 0; i < 8; ++i) { s += ss[i]; sq += ssq[i]; }
    float mean = s * (1.f / DD);
    float var  = sq * (1.f / DD) - mean * mean;
    float rstd = rsqrtf(var + 1e-5f);
    float y0 = (v0 - mean) * rstd * gamma[t]       + beta[t];
    float y1 = (v1 - mean) * rstd * gamma[t + 256] + beta[t + 256];
    __nv_bfloat16 b, sm;
    split1(y0, b, sm); xnb[(size_t)row * DD + t] = b;       xns[(size_t)row * DD + t] = sm;
    split1(y1, b, sm); xnb[(size_t)row * DD + t + 256] = b; xns[(size_t)row * DD + t + 256] = sm;
    xnh[(size_t)row * DD + t]       = __float2half_rn(y0);
    xnh[(size_t)row * DD + t + 256] = __float2half_rn(y1);
}

// ---------------- weight split / convert ----------------
__global__ void wsplit_kernel(const float* __restrict__ wq1, const float* __restrict__ wk1,
                              const float* __restrict__ wv1, const float* __restrict__ wout,
                              __nv_bfloat16* __restrict__ wb, __nv_bfloat16* __restrict__ ws,
                              __half* __restrict__ wh) {
    int idx = blockIdx.x * 256 + threadIdx.x;       // over 4*WSZ/4
    int sel = idx >> 16;
    int off = idx & 65535;
    const float* src = (sel == 0) ? wq1 : (sel == 1) ? wk1 : (sel == 2) ? wv1 : wout;
    float4 v = ((const float4*)src)[off];
    if (sel < 2) {
        uint32_t b01, s01, b23, s23;
        split2(v.x, v.y, b01, s01);
        split2(v.z, v.w, b23, s23);
        ((uint2*)wb)[sel * 65536 + off] = make_uint2(b01, b23);
        ((uint2*)ws)[sel * 65536 + off] = make_uint2(s01, s23);
    } else {
        uint32_t h01 = pack_h2(v.x, v.y), h23 = pack_h2(v.z, v.w);
        ((uint2*)wh)[(sel - 2) * 65536 + off] = make_uint2(h01, h23);
    }
}

// ---------------- bf16x3 mma.sync GEMM (Q/K projections) ----------------
#define GW 20
#define GTB (128 * GW * 4)
#define SM_GEMM (2 * 4 * GTB)

__global__ void __launch_bounds__(256)
gemm_bf16(const __nv_bfloat16* __restrict__ Abig, const __nv_bfloat16* __restrict__ Asml,
          const __nv_bfloat16* __restrict__ wb,   const __nv_bfloat16* __restrict__ ws,
          size_t w_stride, float* __restrict__ Cbase, size_t c_stride) {
    const __nv_bfloat16* Wb = wb + blockIdx.z * w_stride;
    const __nv_bfloat16* Ws = ws + blockIdx.z * w_stride;
    float* C = Cbase + blockIdx.z * c_stride;

    extern __shared__ char smc[];
    uint32_t smb = smem_u32(smc);
    int tid = threadIdx.x;
    int wid = tid >> 5, lane = tid & 31;
    int wm = wid >> 2, wn = wid & 3;
    int lq = lane >> 2, lm = lane & 3;
    int m0 = blockIdx.y * 128, e0 = blockIdx.x * 128;

    int lrow = tid >> 1;
    int lc2  = (tid & 1) * 2;

    float acc[4][4][4];
    #pragma unroll
    for (int i = 0; i < 4; ++i)
        #pragma unroll
        for (int j = 0; j < 4; ++j)
            #pragma unroll
            for (int q = 0; q < 4; ++q) acc[i][j][q] = 0.f;

    auto load_chunk = [&](int c, int buf) {
        int k0 = c << 5;
        uint32_t base = smb + buf * 4 * GTB;
        const __nv_bfloat16* a0 = Abig + (size_t)(m0 + lrow) * 512 + k0;
        const __nv_bfloat16* a1 = Asml + (size_t)(m0 + lrow) * 512 + k0;
        const __nv_bfloat16* w0 = Wb + (size_t)(e0 + lrow) * 512 + k0;
        const __nv_bfloat16* w1 = Ws + (size_t)(e0 + lrow) * 512 + k0;
        #pragma unroll
        for (int j = 0; j < 2; ++j) {
            int c4 = lc2 + j;
            uint32_t doff = (uint32_t)(lrow * GW + c4 * 4) * 4;
            CP_ASYNC16(base + doff,             a0 + c4 * 8);
            CP_ASYNC16(base + GTB + doff,       a1 + c4 * 8);
            CP_ASYNC16(base + 2 * GTB + doff,   w0 + c4 * 8);
            CP_ASYNC16(base + 3 * GTB + doff,   w1 + c4 * 8);
        }
    };

    load_chunk(0, 0);
    CP_COMMIT();

    const uint32_t* smu = (const uint32_t*)smc;
    for (int c = 0; c < 16; ++c) {
        if (c + 1 < 16) {
            load_chunk(c + 1, (c + 1) & 1);
            CP_COMMIT();
            CP_WAIT(1);
        } else {
            CP_WAIT(0);
        }
        __syncthreads();
        const uint32_t* Abu = smu + (c & 1) * 4 * (GTB / 4);
        const uint32_t* Asu = Abu + GTB / 4;
        const uint32_t* Wbu = Abu + 2 * (GTB / 4);
        const uint32_t* Wsu = Abu + 3 * (GTB / 4);
        #pragma unroll
        for (int ks = 0; ks < 2; ++ks) {
            int kb = ks * 8;
            uint32_t ab[4][4], as_[4][4], bb[4][2], bs[4][2];
            #pragma unroll
            for (int mt = 0; mt < 4; ++mt) {
                int r = wm * 64 + mt * 16 + lq;
                ab[mt][0] = Abu[r * GW + kb + lm];
                ab[mt][1] = Abu[(r + 8) * GW + kb + lm];
                ab[mt][2] = Abu[r * GW + kb + lm + 4];
                ab[mt][3] = Abu[(r + 8) * GW + kb + lm + 4];
                as_[mt][0] = Asu[r * GW + kb + lm];
                as_[mt][1] = Asu[(r + 8) * GW + kb + lm];
                as_[mt][2] = Asu[r * GW + kb + lm + 4];
                as_[mt][3] = Asu[(r + 8) * GW + kb + lm + 4];
            }
            #pragma unroll
            for (int nt = 0; nt < 4; ++nt) {
                int n = wn * 32 + nt * 8 + lq;
                bb[nt][0] = Wbu[n * GW + kb + lm];
                bb[nt][1] = Wbu[n * GW + kb + lm + 4];
                bs[nt][0] = Wsu[n * GW + kb + lm];
                bs[nt][1] = Wsu[n * GW + kb + lm + 4];
            }
            #pragma unroll
            for (int mt = 0; mt < 4; ++mt)
                #pragma unroll
                for (int nt = 0; nt < 4; ++nt) {
                    mma_bf16(acc[mt][nt], ab[mt],  bb[nt]);
                    mma_bf16(acc[mt][nt], as_[mt], bb[nt]);
                    mma_bf16(acc[mt][nt], ab[mt],  bs[nt]);
                }
        }
        __syncthreads();
    }

    #pragma unroll
    for (int mt = 0; mt < 4; ++mt) {
        int r0 = m0 + wm * 64 + mt * 16 + lq;
        #pragma unroll
        for (int nt = 0; nt < 4; ++nt) {
            int c0 = e0 + wn * 32 + nt * 8 + lm * 2;
            *(float2*)(C + (size_t)r0 * 512 + c0)       = make_float2(acc[mt][nt][0], acc[mt][nt][1]);
            *(float2*)(C + (size_t)(r0 + 8) * 512 + c0) = make_float2(acc[mt][nt][2], acc[mt][nt][3]);
        }
    }
}

// ---------------- single-pass fp16 GEMM (V proj + output proj) ----------------
__global__ void __launch_bounds__(256)
gemm_fp16(const __half* __restrict__ A, const __half* __restrict__ W,
          float* __restrict__ C) {
    extern __shared__ char smc[];
    uint32_t smb = smem_u32(smc);
    int tid = threadIdx.x;
    int wid = tid >> 5, lane = tid & 31;
    int wm = wid >> 2, wn = wid & 3;
    int lq = lane >> 2, lm = lane & 3;
    int m0 = blockIdx.y * 128, e0 = blockIdx.x * 128;

    int lrow = tid >> 1;
    int lc2  = (tid & 1) * 2;

    float acc[4][4][4];
    #pragma unroll
    for (int i = 0; i < 4; ++i)
        #pragma unroll
        for (int j = 0; j < 4; ++j)
            #pragma unroll
            for (int q = 0; q < 4; ++q) acc[i][j][q] = 0.f;

    auto load_chunk = [&](int c, int buf) {
        int k0 = c << 5;
        uint32_t base = smb + buf * 2 * GTB;
        const __half* a0 = A + (size_t)(m0 + lrow) * 512 + k0;
        const __half* w0 = W + (size_t)(e0 + lrow) * 512 + k0;
        #pragma unroll
        for (int j = 0; j < 2; ++j) {
            int c4 = lc2 + j;
            uint32_t doff = (uint32_t)(lrow * GW + c4 * 4) * 4;
            CP_ASYNC16(base + doff,       a0 + c4 * 8);
            CP_ASYNC16(base + GTB + doff, w0 + c4 * 8);
        }
    };

    load_chunk(0, 0);
    CP_COMMIT();

    const uint32_t* smu = (const uint32_t*)smc;
    for (int c = 0; c < 16; ++c) {
        if (c + 1 < 16) {
            load_chunk(c + 1, (c + 1) & 1);
            CP_COMMIT();
            CP_WAIT(1);
        } else {
            CP_WAIT(0);
        }
        __syncthreads();
        const uint32_t* Au = smu + (c & 1) * 2 * (GTB / 4);
        const uint32_t* Wu = Au + GTB / 4;
        #pragma unroll
        for (int ks = 0; ks < 2; ++ks) {
            int kb = ks * 8;
            uint32_t a[4][4], b[4][2];
            #pragma unroll
            for (int mt = 0; mt < 4; ++mt) {
                int r = wm * 64 + mt * 16 + lq;
                a[mt][0] = Au[r * GW + kb + lm];
                a[mt][1] = Au[(r + 8) * GW + kb + lm];
                a[mt][2] = Au[r * GW + kb + lm + 4];
                a[mt][3] = Au[(r + 8) * GW + kb + lm + 4];
            }
            #pragma unroll
            for (int nt = 0; nt < 4; ++nt) {
                int n = wn * 32 + nt * 8 + lq;
                b[nt][0] = Wu[n * GW + kb + lm];
                b[nt][1] = Wu[n * GW + kb + lm + 4];
            }
            #pragma unroll
            for (int mt = 0; mt < 4; ++mt)
                #pragma unroll
                for (int nt = 0; nt < 4; ++nt)
                    mma_fp16(acc[mt][nt], a[mt], b[nt]);
        }
        __syncthreads();
    }

    #pragma unroll
    for (int mt = 0; mt < 4; ++mt) {
        int r0 = m0 + wm * 64 + mt * 16 + lq;
        #pragma unroll
        for (int nt = 0; nt < 4; ++nt) {
            int c0 = e0 + wn * 32 + nt * 8 + lm * 2;
            *(float2*)(C + (size_t)r0 * 512 + c0)       = make_float2(acc[mt][nt][0], acc[mt][nt][1]);
            *(float2*)(C + (size_t)(r0 + 8) * 512 + c0) = make_float2(acc[mt][nt][2], acc[mt][nt][3]);
        }
    }
}

// ------- depthwise conv q,k (vectorized float4) + split -------
__global__ void conv_qk(const float* __restrict__ lin,
                        const float* __restrict__ wqd, const float* __restrict__ wkd,
                        __nv_bfloat16* __restrict__ qb, __nv_bfloat16* __restrict__ qs,
                        __nv_bfloat16* __restrict__ kb, __nv_bfloat16* __restrict__ ks) {
    int idx = blockIdx.x * 256 + threadIdx.x;      // over ROWS*INNER/4
    int e4 = idx & 127;
    int n  = (idx >> 7) & (NN - 1);
    int b  = idx >> 18;
    int e  = e4 << 2;
    int h = e >> 6, d = e & 63;
    size_t dstu2 = ((((size_t)(b * HH + h) * NN + n) * DH + d)) >> 2;
    const float4* L4 = (const float4*)lin;
    const float4 z4 = make_float4(0.f, 0.f, 0.f, 0.f);
    #pragma unroll
    for (int t = 0; t < 2; ++t) {
        const float4* L = L4 + (size_t)t * (ROWS * INNER / 4);
        const float* wd = t ? wkd : wqd;
        float4 y2 = L[idx];
        float4 y1 = (n >= 1) ? L[idx - 128] : z4;
        float4 y0 = (n >= 2) ? L[idx - 256] : z4;
        float v[4];
        v[0] = wd[e*3+0]*y0.x + wd[e*3+1]*y1.x + wd[e*3+2]*y2.x;
        v[1] = wd[e*3+3]*y0.y + wd[e*3+4]*y1.y + wd[e*3+5]*y2.y;
        v[2] = wd[e*3+6]*y0.z + wd[e*3+7]*y1.z + wd[e*3+8]*y2.z;
        v[3] = wd[e*3+9]*y0.w + wd[e*3+10]*y1.w + wd[e*3+11]*y2.w;
        if (t == 0) { v[0] *= 0.125f; v[1] *= 0.125f; v[2] *= 0.125f; v[3] *= 0.125f; }
        uint32_t b01, s01, b23, s23;
        split2(v[0], v[1], b01, s01);
        split2(v[2], v[3], b23, s23);
        if (t == 0) {
            ((uint2*)qb)[dstu2] = make_uint2(b01, b23);
            ((uint2*)qs)[dstu2] = make_uint2(s01, s23);
        } else {
            ((uint2*)kb)[dstu2] = make_uint2(b01, b23);
            ((uint2*)ks)[dstu2] = make_uint2(s01, s23);
        }
    }
}

// ------- depthwise conv for v + TRANSPOSED fp16 output -------
__global__ void conv_v(const float* __restrict__ lin2, const float* __restrict__ wvd,
                       __half* __restrict__ vhT) {
    __shared__ float tile[34 * 33];
    int b = blockIdx.z, e0 = blockIdx.y * 32, n0 = blockIdx.x * 32;
    int tid = threadIdx.x;
    for (int i = tid; i < 34 * 32; i += 256) {
        int r = i >> 5, c = i & 31;
        int n = n0 - 2 + r;
        tile[r * 33 + c] = (n >= 0) ? lin2[((size_t)b * NN + n) * INNER + e0 + c] : 0.f;
    }
    __syncthreads();
    int nl = tid & 31;
    #pragma unroll
    for (int p = 0; p < 4; ++p) {
        int el = (tid >> 5) + p * 8;
        int eg = e0 + el;
        int h = eg >> 6, d = eg & 63;
        float y0 = tile[nl * 33 + el];
        float y1 = tile[(nl + 1) * 33 + el];
        float y2 = tile[(nl + 2) * 33 + el];
        float v = wvd[eg * 3 + 0] * y0 + wvd[eg * 3 + 1] * y1 + wvd[eg * 3 + 2] * y2;
        size_t dst = ((size_t)(b * HH + h) * DH + d) * NN + n0 + nl;
        vhT[dst] = __float2half_rn(v);
    }
}

// ---- Flash attention: S bf16x3, PV fp16 single-pass, prefetch ----
#define AW 36
#define SETU (3 * 64 * AW)              // u32 per buffer set (Kb,Ks,Vh)
#define SMEM_ATTN (2 * SETU * 4)        // 55296 B -> 3 blocks/SM

__global__ void __launch_bounds__(128, 3)
attn_kernel(const __nv_bfloat16* __restrict__ qb_g, const __nv_bfloat16* __restrict__ qs_g,
            const __nv_bfloat16* __restrict__ kb_g, const __nv_bfloat16* __restrict__ ks_g,
            const __half* __restrict__ vhT_g,
            __half* __restrict__ oh_g) {
    extern __shared__ uint32_t smu[];
    uint32_t smb = smem_u32(smu);

    int qt = gridDim.x - 1 - blockIdx.x;   // big tiles first
    int bh = blockIdx.y;
    int b = bh >> 3, h = bh & 7;
    int qs0 = qt * 64;

    int tid = threadIdx.x;
    int wid = tid >> 5, lane = tid & 31;
    int lq = lane >> 2, lm = lane & 3;
    int wr = wid * 16;

    const uint32_t* qbu = (const uint32_t*)qb_g + (size_t)bh * NN * 32;
    const uint32_t* qsu = (const uint32_t*)qs_g + (size_t)bh * NN * 32;
    int r0 = qs0 + wr + lq;
    uint32_t qbf[4][4], qsf[4][4];
    #pragma unroll
    for (int ks = 0; ks < 4; ++ks) {
        qbf[ks][0] = qbu[(size_t)r0 * 32 + ks * 8 + lm];
        qbf[ks][1] = qbu[(size_t)(r0 + 8) * 32 + ks * 8 + lm];
        qbf[ks][2] = qbu[(size_t)r0 * 32 + ks * 8 + lm + 4];
        qbf[ks][3] = qbu[(size_t)(r0 + 8) * 32 + ks * 8 + lm + 4];
        qsf[ks][0] = qsu[(size_t)r0 * 32 + ks * 8 + lm];
        qsf[ks][1] = qsu[(size_t)(r0 + 8) * 32 + ks * 8 + lm];
        qsf[ks][2] = qsu[(size_t)r0 * 32 + ks * 8 + lm + 4];
        qsf[ks][3] = qsu[(size_t)(r0 + 8) * 32 + ks * 8 + lm + 4];
    }

    float acc_o[8][4];
    #pragma unroll
    for (int nt = 0; nt < 8; ++nt)
        #pragma unroll
        for (int q = 0; q < 4; ++q) acc_o[nt][q] = 0.f;
    float m0r = -1e30f, m1r = -1e30f, l0r = 0.f, l1r = 0.f;
    float slope = exp2f(-(float)(h + 1));
    int ig0 = r0, ig1 = r0 + 8;

    const char* kbp = (const char*)(kb_g + (size_t)bh * NN * DH);
    const char* ksp = (const char*)(ks_g + (size_t)bh * NN * DH);
    const char* vhp = (const char*)(vhT_g + (size_t)bh * DH * NN);

    auto load_tile = [&](int t, int buf) {
        int ks0 = t * 64;
        uint32_t base = smb + (uint32_t)buf * (SETU * 4);
        #pragma unroll
        for (int i = 0; i < 4; ++i) {
            int idx = i * 128 + tid;
            int r = idx >> 3, c = idx & 7;
            uint32_t doff = (uint32_t)(r * AW + c * 4) * 4;
            CP_ASYNC16(base + doff,         kbp + (size_t)(ks0 + r) * 128 + c * 16);
            CP_ASYNC16(base + 9216 + doff,  ksp + (size_t)(ks0 + r) * 128 + c * 16);
            CP_ASYNC16(base + 18432 + doff, vhp + (size_t)r * (NN * 2) + ks0 * 2 + c * 16);
        }
    };

    int ntile = qt + 1;
    load_tile(0, 0);
    CP_COMMIT();
    for (int t = 0; t < ntile; ++t) {
        int buf = t & 1;
        if (t + 1 < ntile) {
            load_tile(t + 1, buf ^ 1);
            CP_COMMIT();
            CP_WAIT(1);
        } else {
            CP_WAIT(0);
        }
        __syncthreads();
        const uint32_t* Kb = smu + buf * SETU;
        const uint32_t* Ks = Kb + 2304;
        const uint32_t* Vh = Kb + 4608;
        int ks0 = t * 64;

        // S = Q K^T (bf16x3, 4 k16-steps)
        float acc_s[8][4];
        #pragma unroll
        for (int nt = 0; nt < 8; ++nt)
            #pragma unroll
            for (int q = 0; q < 4; ++q) acc_s[nt][q] = 0.f;
        #pragma unroll
        for (int ks = 0; ks < 4; ++ks) {
            int kc = ks * 8;
            #pragma unroll
            for (int nt = 0; nt < 8; ++nt) {
                int rb = (nt * 8 + lq) * AW + kc + lm;
                uint32_t bb[2], bs[2];
                bb[0] = Kb[rb];     bb[1] = Kb[rb + 4];
                bs[0] = Ks[rb];     bs[1] = Ks[rb + 4];
                mma_bf16(acc_s[nt], qbf[ks], bb);
                mma_bf16(acc_s[nt], qsf[ks], bb);
                mma_bf16(acc_s[nt], qbf[ks], bs);
            }
        }

        // bias + causal mask
        #pragma unroll
        for (int nt = 0; nt < 8; ++nt) {
            int jg = ks0 + nt * 8 + lm * 2;
            acc_s[nt][0] = (jg     <= ig0) ? acc_s[nt][0] - slope * (float)(ig0 - jg)     : -1e30f;
            acc_s[nt][1] = (jg + 1 <= ig0) ? acc_s[nt][1] - slope * (float)(ig0 - jg - 1) : -1e30f;
            acc_s[nt][2] = (jg     <= ig1) ? acc_s[nt][2] - slope * (float)(ig1 - jg)     : -1e30f;
            acc_s[nt][3] = (jg + 1 <= ig1) ? acc_s[nt][3] - slope * (float)(ig1 - jg - 1) : -1e30f;
        }

        // online softmax (quad reduce)
        float rm0 = -1e30f, rm1 = -1e30f;
        #pragma unroll
        for (int nt = 0; nt < 8; ++nt) {
            rm0 = fmaxf(rm0, fmaxf(acc_s[nt][0], acc_s[nt][1]));
            rm1 = fmaxf(rm1, fmaxf(acc_s[nt][2], acc_s[nt][3]));
        }
        rm0 = fmaxf(rm0, __shfl_xor_sync(0xffffffffu, rm0, 1));
        rm0 = fmaxf(rm0, __shfl_xor_sync(0xffffffffu, rm0, 2));
        rm1 = fmaxf(rm1, __shfl_xor_sync(0xffffffffu, rm1, 1));
        rm1 = fmaxf(rm1, __shfl_xor_sync(0xffffffffu, rm1, 2));
        float mn0 = fmaxf(m0r, rm0), mn1 = fmaxf(m1r, rm1);
        float al0 = __expf(m0r - mn0), al1 = __expf(m1r - mn1);
        float ls0 = 0.f, ls1 = 0.f;
        #pragma unroll
        for (int nt = 0; nt < 8; ++nt) {
            acc_s[nt][0] = __expf(acc_s[nt][0] - mn0);
            acc_s[nt][1] = __expf(acc_s[nt][1] - mn0);
            acc_s[nt][2] = __expf(acc_s[nt][2] - mn1);
            acc_s[nt][3] = __expf(acc_s[nt][3] - mn1);
            ls0 += acc_s[nt][0] + acc_s[nt][1];
            ls1 += acc_s[nt][2] + acc_s[nt][3];
        }
        ls0 += __shfl_xor_sync(0xffffffffu, ls0, 1);
        ls0 += __shfl_xor_sync(0xffffffffu, ls0, 2);
        ls1 += __shfl_xor_sync(0xffffffffu, ls1, 1);
        ls1 += __shfl_xor_sync(0xffffffffu, ls1, 2);
        l0r = l0r * al0 + ls0;  m0r = mn0;
        l1r = l1r * al1 + ls1;  m1r = mn1;
        #pragma unroll
        for (int nt = 0; nt < 8; ++nt) {
            acc_o[nt][0] *= al0; acc_o[nt][1] *= al0;
            acc_o[nt][2] *= al1; acc_o[nt][3] *= al1;
        }

        // O += P @ V : single-pass fp16
        #pragma unroll
        for (int ks = 0; ks < 4; ++ks) {
            uint32_t pa[4];
            pa[0] = pack_h2(acc_s[2*ks][0],   acc_s[2*ks][1]);
            pa[1] = pack_h2(acc_s[2*ks][2],   acc_s[2*ks][3]);
            pa[2] = pack_h2(acc_s[2*ks+1][0], acc_s[2*ks+1][1]);
            pa[3] = pack_h2(acc_s[2*ks+1][2], acc_s[2*ks+1][3]);
            int kc = ks * 8;
            #pragma unroll
            for (int nt = 0; nt < 8; ++nt) {
                int rb = (nt * 8 + lq) * AW + kc + lm;
                uint32_t vh_[2];
                vh_[0] = Vh[rb];     vh_[1] = Vh[rb + 4];
                mma_fp16(acc_o[nt], pa, vh_);
            }
        }
        __syncthreads();
    }

    // normalize, write fp16 pairs
    float inv0 = 1.f / l0r, inv1 = 1.f / l1r;
    uint32_t* ohu = (uint32_t*)oh_g;
    size_t base0 = (((size_t)b * NN + r0) * INNER + h * DH) >> 1;
    size_t base1 = (((size_t)b * NN + r0 + 8) * INNER + h * DH) >> 1;
    #pragma unroll
    for (int nt = 0; nt < 8; ++nt) {
        ohu[base0 + nt * 4 + lm] = pack_h2(acc_o[nt][0] * inv0, acc_o[nt][1] * inv0);
        ohu[base1 + nt * 4 + lm] = pack_h2(acc_o[nt][2] * inv1, acc_o[nt][3] * inv1);
    }
}

extern "C" void kernel_launch(void* const* d_in, const int* in_sizes, int n_in,
                              void* d_out, int out_size) {
    const float* x     = (const float*)d_in[0];
    const float* gamma = (const float*)d_in[1];
    const float* beta  = (const float*)d_in[2];
    const float* wq1   = (const float*)d_in[3];
    const float* wqd   = (const float*)d_in[4];
    const float* wk1   = (const float*)d_in[5];
    const float* wkd   = (const float*)d_in[6];
    const float* wv1   = (const float*)d_in[7];
    const float* wvd   = (const float*)d_in[8];
    const float* wout  = (const float*)d_in[9];
    float* out = (float*)d_out;

    float* lin;
    __half *vhT, *xnh, *wh, *oh;
    __nv_bfloat16 *xnb, *xns, *wb, *ws, *qb, *qs, *kb, *ks;
    cudaGetSymbolAddress((void**)&lin, g_lin);
    cudaGetSymbolAddress((void**)&xnb, g_xnb);  cudaGetSymbolAddress((void**)&xns, g_xns);
    cudaGetSymbolAddress((void**)&xnh, g_xnh);
    cudaGetSymbolAddress((void**)&wb,  g_wb);   cudaGetSymbolAddress((void**)&ws,  g_ws);
    cudaGetSymbolAddress((void**)&wh,  g_wh);
    cudaGetSymbolAddress((void**)&qb,  g_qb);   cudaGetSymbolAddress((void**)&qs,  g_qs);
    cudaGetSymbolAddress((void**)&kb,  g_kb);   cudaGetSymbolAddress((void**)&ks,  g_ks);
    cudaGetSymbolAddress((void**)&vhT, g_vhT);
    cudaGetSymbolAddress((void**)&oh,  g_oh);

    cudaFuncSetAttribute(gemm_bf16, cudaFuncAttributeMaxDynamicSharedMemorySize, SM_GEMM);
    cudaFuncSetAttribute(gemm_fp16, cudaFuncAttributeMaxDynamicSharedMemorySize, SM_GEMM / 2);
    cudaFuncSetAttribute(attn_kernel, cudaFuncAttributeMaxDynamicSharedMemorySize, SMEM_ATTN);

    // 1) LayerNorm (split bf16 + fp16 out) + weight split/convert
    ln_kernel<<<ROWS, 256>>>(x, gamma, beta, xnb, xns, xnh);
    wsplit_kernel<<<WSZ / 256, 256>>>(wq1, wk1, wv1, wout, wb, ws, wh);

    // 2) q/k projections (bf16x3, z=2) + v projection (fp16 single-pass)
    dim3 g1(4, 32, 2);
    gemm_bf16<<<g1, 256, SM_GEMM>>>(xnb, xns, wb, ws, WSZ, lin, (size_t)ROWS * INNER);
    dim3 g2(4, 32, 1);
    gemm_fp16<<<g2, 256, SM_GEMM / 2>>>(xnh, wh, lin + 2 * (size_t)ROWS * INNER);

    // 3) depthwise conv + split (q/k d-major bf16, v transposed fp16)
    conv_qk<<<(ROWS * INNER / 4) / 256, 256>>>(lin, wqd, wkd, qb, qs, kb, ks);
    conv_v<<<dim3(NN / 32, INNER / 32, BB), 256>>>(lin + 2 * (size_t)ROWS * INNER, wvd, vhT);

    // 4) flash attention (S bf16x3, PV fp16) -> fp16 out
    attn_kernel<<<dim3(NN / 64, BB * HH), 128, SMEM_ATTN>>>(qb, qs, kb, ks, vhT, oh);

    // 5) output projection (fp16 single-pass) straight into d_out
    gemm_fp16<<<g2, 256, SM_GEMM / 2>>>(oh, wh + WSZ, out);
}